// round 6
// baseline (speedup 1.0000x reference)
#include <cuda_runtime.h>

#define BS 32
#define NA 8400
#define NC 80
#define NG 48
#define TK 13
#define EPSF 1e-9f
#define CAP 1024
#define GB 16
#define NBIN (GB*GB)
#define MAXCLAIM (BS*NG*TK)   // 19968

#define OFF_LAB 0
#define OFF_BOX (BS*NA)
#define OFF_SCR (OFF_BOX + BS*NA*4)
#define OFF_FG  (OFF_SCR + BS*NA*NC)
#define OFF_TGT (OFF_FG + BS*NA)

#define NSCR4   (BS*NA*NC/4)                 // 5,376,000 float4 zeros
#define ZPB     (256*16)                     // float4 zeroed per zero-block
#define ZBLK    ((NSCR4 + ZPB - 1)/ZPB)      // 1313
#define NROW    (BS*NG)                      // 1536 assign rows

__device__ int      g_bin_off[NBIN+1];
__device__ int      g_bin_anchor[NA];
__device__ float2   g_anc_sorted[NA];
__device__ int      g_count[BS*NA];
__device__ int      g_cand_n[BS*NA];
__device__ float    g_cand_align[BS*NA];
__device__ float    g_cand_ovl[BS*NA];
__device__ unsigned g_pos_align[BS*NG];
__device__ unsigned g_pos_ovl[BS*NG];
__device__ int      g_claim[MAXCLAIM];
__device__ int      g_claim_cnt;

__device__ __forceinline__ float iou_f(float4 g, float garea, float4 p, float parea) {
    float iw = fminf(g.z, p.z) - fmaxf(g.x, p.x); iw = fmaxf(iw, 0.f);
    float ih = fminf(g.w, p.w) - fmaxf(g.y, p.y); ih = fmaxf(ih, 0.f);
    float inter = iw * ih;
    float uni = garea + parea - inter + EPSF;
    return inter / uni;
}

__device__ __forceinline__ int binclamp(float v) {
    int x = (int)(v * GB);
    return min(max(x, 0), GB - 1);
}

// ---------------------------------------------------------------------------
// 1) prep: block 0 = anchor binning (count/scan/fill); rest zero scratch.
// ---------------------------------------------------------------------------
__global__ void k_prep(const float2* __restrict__ anc) {
    int t = threadIdx.x;
    if (blockIdx.x == 0) {
        __shared__ int s_cnt[NBIN];
        __shared__ int s_scan[NBIN];
        __shared__ int s_fill[NBIN];
        if (t < NBIN) { s_cnt[t] = 0; s_fill[t] = 0; }
        if (t == 0) g_claim_cnt = 0;
        __syncthreads();
        for (int a = t; a < NA; a += 1024) {
            float2 p = anc[a];
            atomicAdd(&s_cnt[binclamp(p.y)*GB + binclamp(p.x)], 1);
        }
        __syncthreads();
        if (t < NBIN) s_scan[t] = s_cnt[t];
        __syncthreads();
        #pragma unroll
        for (int off = 1; off < NBIN; off <<= 1) {
            int v = 0;
            if (t < NBIN && t >= off) v = s_scan[t - off];
            __syncthreads();
            if (t < NBIN) s_scan[t] += v;
            __syncthreads();
        }
        if (t < NBIN) g_bin_off[t] = s_scan[t] - s_cnt[t];
        if (t == 0)   g_bin_off[NBIN] = NA;
        __syncthreads();
        for (int a = t; a < NA; a += 1024) {
            float2 p = anc[a];
            int bin = binclamp(p.y)*GB + binclamp(p.x);
            int pos = (s_scan[bin] - s_cnt[bin]) + atomicAdd(&s_fill[bin], 1);
            g_bin_anchor[pos] = a;
            g_anc_sorted[pos] = p;
        }
    } else {
        int gid = (blockIdx.x - 1) * 1024 + t;
        if (gid < BS*NA) { g_count[gid] = 0; g_cand_n[gid] = -1; }
        if (gid < BS*NG) { g_pos_align[gid] = 0u; g_pos_ovl[gid] = 0u; }
    }
}

// ---------------------------------------------------------------------------
// 2) fused: assign rows (blocks [0,NROW)) + score zero-fill (blocks >= NROW).
//    The streaming-store zero blocks co-run with the compute-heavy assign
//    blocks, hiding the 86MB fill behind the candidate scans.
// ---------------------------------------------------------------------------
__global__ void k_assign(const float* __restrict__ pd_scores,
                         const float4* __restrict__ pd_bbox,
                         const float2* __restrict__ anc,
                         const float* __restrict__ mask_gt,
                         const int* __restrict__ gt_labels,
                         const float4* __restrict__ gt_bbox,
                         float* __restrict__ out) {
    int tid = threadIdx.x;

    if (blockIdx.x >= NROW) {                 // zero-fill blocks
        float4* scr = (float4*)(out + OFF_SCR);
        int base = (blockIdx.x - NROW) * ZPB + tid;
        float4 z = make_float4(0.f, 0.f, 0.f, 0.f);
        #pragma unroll
        for (int it = 0; it < 16; it++) {
            int i = base + it * 256;
            if (i < NSCR4) scr[i] = z;
        }
        return;
    }

    __shared__ unsigned long long s_list[CAP];
    __shared__ int   s_cnt;
    __shared__ int   s_win[TK];
    __shared__ float s_val[TK];
    __shared__ int   s_picks;

    int row = blockIdx.x;
    int b = row / NG, n = row % NG;

    if (mask_gt[row] <= 0.f) return;

    float4 g = gt_bbox[row];
    float garea = (g.z - g.x) * (g.w - g.y + EPSF);
    int lab = gt_labels[row];
    if (tid == 0) s_cnt = 0;
    __syncthreads();

    int bx0 = binclamp(g.x), bx1 = binclamp(g.z);
    int by0 = binclamp(g.y), by1 = binclamp(g.w);

    for (int by = by0; by <= by1; by++) {
        int s0 = g_bin_off[by*GB + bx0];
        int s1 = g_bin_off[by*GB + bx1 + 1];
        for (int i = s0 + tid; i < s1; i += 256) {
            float2 ap = g_anc_sorted[i];
            float dmin = fminf(fminf(ap.x - g.x, ap.y - g.y),
                               fminf(g.z - ap.x, g.w - ap.y));
            if (dmin > EPSF) {
                int a = g_bin_anchor[i];
                float4 p = pd_bbox[b*NA + a];
                float parea = (p.z - p.x) * (p.w - p.y + EPSF);
                float iou = iou_f(g, garea, p, parea);
                if (iou > 0.f) {
                    float sc = __ldg(&pd_scores[(b*NA + a)*NC + lab]);
                    float o2 = iou * iou;
                    float m  = sc * o2*o2*o2;
                    if (m > 0.f) {
                        int pos = atomicAdd(&s_cnt, 1);
                        if (pos < CAP)
                            s_list[pos] = ((unsigned long long)__float_as_uint(m) << 32)
                                        | (unsigned)(65535 - a);
                    }
                }
            }
        }
    }
    __syncthreads();
    int cnt = min(s_cnt, CAP);

    if (tid < 32) {
        int picks = 0;
        for (int k = 0; k < TK; k++) {
            unsigned long long bv = 0ull; int bi = -1;
            for (int i = tid; i < cnt; i += 32) {
                unsigned long long v = s_list[i];
                if (v > bv) { bv = v; bi = i; }
            }
            #pragma unroll
            for (int off = 16; off; off >>= 1) {
                unsigned long long ov = __shfl_xor_sync(0xffffffffu, bv, off);
                int oi = __shfl_xor_sync(0xffffffffu, bi, off);
                if (ov > bv) { bv = ov; bi = oi; }
            }
            if (bv == 0ull) break;
            if (tid == 0) {
                s_win[k] = 65535 - (int)(bv & 0xFFFFull);
                s_val[k] = __uint_as_float((unsigned)(bv >> 32));
                s_list[bi] = 0ull;
            }
            picks++;
            __syncwarp();
        }
        if (tid == 0) {
            s_picks = picks;
            int k = picks, a = 0;
            while (k < TK) {
                bool used = false;
                for (int t = 0; t < picks; t++) if (s_win[t] == a) { used = true; break; }
                if (!used) { s_win[k] = a; s_val[k] = 0.f; k++; }
                a++;
            }
        }
        __syncwarp();

        if (tid < TK) {
            int   idx = s_win[tid];
            float val = s_val[tid];
            bool claim;
            float4 p;
            if (tid < s_picks) {
                claim = true;                    // m>0 implies in-box
                p = pd_bbox[b*NA + idx];
            } else {
                float2 ap = anc[idx];            // filler: in-box test required
                float dmin = fminf(fminf(ap.x - g.x, ap.y - g.y),
                                   fminf(g.z - ap.x, g.w - ap.y));
                claim = dmin > EPSF;
                if (claim) p = pd_bbox[b*NA + idx];
            }
            if (claim) {
                float parea = (p.z - p.x)*(p.w - p.y + EPSF);
                float iou = iou_f(g, garea, p, parea);
                int pp = b*NA + idx;
                atomicAdd(&g_count[pp], 1);
                int cp = atomicAdd(&g_claim_cnt, 1);
                if (cp < MAXCLAIM) g_claim[cp] = pp;
                // benign race: multi anchors fully rewritten in k_finalize
                g_cand_n[pp]     = n;
                g_cand_align[pp] = val;
                g_cand_ovl[pp]   = iou;
            }
        }
    }
}

// ---------------------------------------------------------------------------
// 3) finalize: resolve multi anchors (idempotent duplicates) + pos maxima
// ---------------------------------------------------------------------------
__global__ void k_finalize(const float* __restrict__ pd_scores,
                           const float4* __restrict__ pd_bbox,
                           const int* __restrict__ gt_labels,
                           const float4* __restrict__ gt_bbox) {
    int gid = blockIdx.x*256 + threadIdx.x;
    int mc = min(g_claim_cnt, MAXCLAIM);
    if (gid >= mc) return;
    int p = g_claim[gid];
    int b = p / NA, a = p % NA;
    int cn; float al, ov;
    if (g_count[p] > 1) {
        float4 pb = pd_bbox[p];
        float parea = (pb.z - pb.x)*(pb.w - pb.y + EPSF);
        float bv = -1.f; int bn = 0;
        for (int n = 0; n < NG; n++) {
            float4 gg = gt_bbox[b*NG + n];
            float ga = (gg.z - gg.x)*(gg.w - gg.y + EPSF);
            float v = iou_f(gg, ga, pb, parea);
            if (v > bv) { bv = v; bn = n; }
        }
        float sc = pd_scores[(b*NA + a)*NC + gt_labels[b*NG + bn]];
        float o2 = bv*bv;
        cn = bn; ov = bv; al = sc * o2*o2*o2;
        g_cand_n[p]     = cn;
        g_cand_ovl[p]   = ov;
        g_cand_align[p] = al;
    } else {
        cn = g_cand_n[p];
        al = g_cand_align[p];
        ov = g_cand_ovl[p];
    }
    atomicMax(&g_pos_align[b*NG + cn], __float_as_uint(al));
    atomicMax(&g_pos_ovl[b*NG + cn],   __float_as_uint(ov));
}

// ---------------------------------------------------------------------------
// 4) small outputs, 4 anchors/thread, vectorized loads & stores + sparse
//    one-hot score scatter (region pre-zeroed during k_assign).
// ---------------------------------------------------------------------------
__global__ void k_small(const int* __restrict__ gt_labels,
                        const float4* __restrict__ gt_bbox,
                        float* __restrict__ out) {
    int t4 = blockIdx.x*256 + threadIdx.x;
    if (t4 >= BS*NA/4) return;
    int gid0 = t4 * 4;
    int b = gid0 / NA;                       // NA % 4 == 0: group within one batch

    int4   cn4 = ((const int4*)g_cand_n)[t4];
    float4 al4 = ((const float4*)g_cand_align)[t4];
    int cns[4] = {cn4.x, cn4.y, cn4.z, cn4.w};
    float als[4] = {al4.x, al4.y, al4.z, al4.w};

    float labf[4], fgf[4], tgtf[4];
    #pragma unroll
    for (int j = 0; j < 4; j++) {
        int cn = cns[j];
        bool fg = cn >= 0;
        int tgt = fg ? cn : 0;
        int lab = gt_labels[b*NG + tgt];
        labf[j] = (float)lab;
        fgf[j]  = fg ? 1.f : 0.f;
        tgtf[j] = (float)tgt;
        ((float4*)(out + OFF_BOX))[gid0 + j] = gt_bbox[b*NG + tgt];
        if (fg) {
            float pa = __uint_as_float(g_pos_align[b*NG + cn]);
            float po = __uint_as_float(g_pos_ovl[b*NG + cn]);
            float norm = als[j] * po / (pa + EPSF);
            out[OFF_SCR + (gid0 + j)*NC + lab] = norm;
        }
    }
    ((float4*)(out + OFF_LAB))[t4] = make_float4(labf[0], labf[1], labf[2], labf[3]);
    ((float4*)(out + OFF_FG ))[t4] = make_float4(fgf[0],  fgf[1],  fgf[2],  fgf[3]);
    ((float4*)(out + OFF_TGT))[t4] = make_float4(tgtf[0], tgtf[1], tgtf[2], tgtf[3]);
}

// ---------------------------------------------------------------------------
extern "C" void kernel_launch(void* const* d_in, const int* in_sizes, int n_in,
                              void* d_out, int out_size) {
    const float*  pd_scores = (const float*)d_in[0];
    const float4* pd_bbox   = (const float4*)d_in[1];
    const float2* anc       = (const float2*)d_in[2];
    const int*    gt_labels = (const int*)d_in[3];
    const float4* gt_bbox   = (const float4*)d_in[4];
    const float*  mask_gt   = (const float*)d_in[5];
    float* out = (float*)d_out;
    (void)in_sizes; (void)n_in; (void)out_size;

    k_prep<<<1 + (BS*NA + 1023)/1024, 1024>>>(anc);
    k_assign<<<NROW + ZBLK, 256>>>(pd_scores, pd_bbox, anc, mask_gt,
                                   gt_labels, gt_bbox, out);
    k_finalize<<<(MAXCLAIM + 255)/256, 256>>>(pd_scores, pd_bbox, gt_labels, gt_bbox);
    k_small<<<(BS*NA/4 + 255)/256, 256>>>(gt_labels, gt_bbox, out);
}

// round 7
// speedup vs baseline: 1.2630x; 1.2630x over previous
#include <cuda_runtime.h>

#define BS 32
#define NA 8400
#define NC 80
#define NG 48
#define TK 13
#define EPSF 1e-9f
#define CAP 1024
#define GB 16
#define NBIN (GB*GB)
#define MAXCLAIM (BS*NG*TK)   // 19968

#define OFF_LAB 0
#define OFF_BOX (BS*NA)
#define OFF_SCR (OFF_BOX + BS*NA*4)
#define OFF_FG  (OFF_SCR + BS*NA*NC)
#define OFF_TGT (OFF_FG + BS*NA)

#define NSCR4   (BS*NA*NC/4)                 // 5,376,000 float4 zeros
#define ZS_BLK  263                          // scratch-zero blocks (268800/1024)
#define ZS_PER  4
#define ZSC_BLK ((NSCR4 + 1024*ZS_PER - 1)/(1024*ZS_PER))   // 1313

__device__ int      g_bin_off[NBIN+1];
__device__ int      g_bin_anchor[NA];
__device__ float2   g_anc_sorted[NA];
__device__ int      g_count[BS*NA];
__device__ int      g_cand_n[BS*NA];
__device__ float    g_cand_align[BS*NA];
__device__ float    g_cand_ovl[BS*NA];
__device__ unsigned g_pos_align[BS*NG];
__device__ unsigned g_pos_ovl[BS*NG];
__device__ int      g_claim[MAXCLAIM];
__device__ int      g_claim_cnt;

__device__ __forceinline__ float iou_f(float4 g, float garea, float4 p, float parea) {
    float iw = fminf(g.z, p.z) - fmaxf(g.x, p.x); iw = fmaxf(iw, 0.f);
    float ih = fminf(g.w, p.w) - fmaxf(g.y, p.y); ih = fmaxf(ih, 0.f);
    float inter = iw * ih;
    float uni = garea + parea - inter + EPSF;
    return inter / uni;
}

__device__ __forceinline__ int binclamp(float v) {
    int x = (int)(v * GB);
    return min(max(x, 0), GB - 1);
}

// ---------------------------------------------------------------------------
// 1) prep. block 0: anchor binning. blocks [1,ZS_BLK]: zero scratch.
//    blocks > ZS_BLK: stream-fill the 86MB target_scores region with zeros
//    using evict-first stores (write-once data; keep L2 for the binning work).
// ---------------------------------------------------------------------------
__global__ void k_prep(const float2* __restrict__ anc, float* __restrict__ out) {
    int t = threadIdx.x;
    if (blockIdx.x == 0) {
        __shared__ int s_cnt[NBIN];
        __shared__ int s_scan[NBIN];
        __shared__ int s_fill[NBIN];
        if (t < NBIN) { s_cnt[t] = 0; s_fill[t] = 0; }
        if (t == 0) g_claim_cnt = 0;
        __syncthreads();
        for (int a = t; a < NA; a += 1024) {
            float2 p = anc[a];
            atomicAdd(&s_cnt[binclamp(p.y)*GB + binclamp(p.x)], 1);
        }
        __syncthreads();
        if (t < NBIN) s_scan[t] = s_cnt[t];
        __syncthreads();
        #pragma unroll
        for (int off = 1; off < NBIN; off <<= 1) {
            int v = 0;
            if (t < NBIN && t >= off) v = s_scan[t - off];
            __syncthreads();
            if (t < NBIN) s_scan[t] += v;
            __syncthreads();
        }
        if (t < NBIN) g_bin_off[t] = s_scan[t] - s_cnt[t];
        if (t == 0)   g_bin_off[NBIN] = NA;
        __syncthreads();
        for (int a = t; a < NA; a += 1024) {
            float2 p = anc[a];
            int bin = binclamp(p.y)*GB + binclamp(p.x);
            int pos = (s_scan[bin] - s_cnt[bin]) + atomicAdd(&s_fill[bin], 1);
            g_bin_anchor[pos] = a;
            g_anc_sorted[pos] = p;
        }
    } else if (blockIdx.x <= ZS_BLK) {
        int gid = (blockIdx.x - 1) * 1024 + t;
        if (gid < BS*NA) { g_count[gid] = 0; g_cand_n[gid] = -1; }
        if (gid < BS*NG) { g_pos_align[gid] = 0u; g_pos_ovl[gid] = 0u; }
    } else {
        float4* scr = (float4*)(out + OFF_SCR);
        int base = (blockIdx.x - 1 - ZS_BLK) * 1024 * ZS_PER + t;
        float4 z = make_float4(0.f, 0.f, 0.f, 0.f);
        #pragma unroll
        for (int it = 0; it < ZS_PER; it++) {
            int i = base + it * 1024;
            if (i < NSCR4) __stcs(&scr[i], z);
        }
    }
}

// ---------------------------------------------------------------------------
// 2) fused sparse metric + top-13 + scatter + claim-list append
// ---------------------------------------------------------------------------
__global__ void k_assign(const float* __restrict__ pd_scores,
                         const float4* __restrict__ pd_bbox,
                         const float2* __restrict__ anc,
                         const float* __restrict__ mask_gt,
                         const int* __restrict__ gt_labels,
                         const float4* __restrict__ gt_bbox) {
    __shared__ unsigned long long s_list[CAP];
    __shared__ int   s_cnt;
    __shared__ int   s_win[TK];
    __shared__ float s_val[TK];
    __shared__ int   s_picks;

    int row = blockIdx.x;
    int b = row / NG, n = row % NG;
    int tid = threadIdx.x;

    if (mask_gt[row] <= 0.f) return;

    float4 g = gt_bbox[row];
    float garea = (g.z - g.x) * (g.w - g.y + EPSF);
    int lab = gt_labels[row];
    if (tid == 0) s_cnt = 0;
    __syncthreads();

    int bx0 = binclamp(g.x), bx1 = binclamp(g.z);
    int by0 = binclamp(g.y), by1 = binclamp(g.w);

    for (int by = by0; by <= by1; by++) {
        int s0 = g_bin_off[by*GB + bx0];
        int s1 = g_bin_off[by*GB + bx1 + 1];
        for (int i = s0 + tid; i < s1; i += 256) {
            float2 ap = g_anc_sorted[i];
            float dmin = fminf(fminf(ap.x - g.x, ap.y - g.y),
                               fminf(g.z - ap.x, g.w - ap.y));
            if (dmin > EPSF) {
                int a = g_bin_anchor[i];
                float4 p = pd_bbox[b*NA + a];
                float parea = (p.z - p.x) * (p.w - p.y + EPSF);
                float iou = iou_f(g, garea, p, parea);
                if (iou > 0.f) {
                    float sc = __ldg(&pd_scores[(b*NA + a)*NC + lab]);
                    float o2 = iou * iou;
                    float m  = sc * o2*o2*o2;
                    if (m > 0.f) {
                        int pos = atomicAdd(&s_cnt, 1);
                        if (pos < CAP)
                            s_list[pos] = ((unsigned long long)__float_as_uint(m) << 32)
                                        | (unsigned)(65535 - a);
                    }
                }
            }
        }
    }
    __syncthreads();
    int cnt = min(s_cnt, CAP);

    if (tid < 32) {
        int picks = 0;
        for (int k = 0; k < TK; k++) {
            unsigned long long bv = 0ull; int bi = -1;
            for (int i = tid; i < cnt; i += 32) {
                unsigned long long v = s_list[i];
                if (v > bv) { bv = v; bi = i; }
            }
            #pragma unroll
            for (int off = 16; off; off >>= 1) {
                unsigned long long ov = __shfl_xor_sync(0xffffffffu, bv, off);
                int oi = __shfl_xor_sync(0xffffffffu, bi, off);
                if (ov > bv) { bv = ov; bi = oi; }
            }
            if (bv == 0ull) break;
            if (tid == 0) {
                s_win[k] = 65535 - (int)(bv & 0xFFFFull);
                s_val[k] = __uint_as_float((unsigned)(bv >> 32));
                s_list[bi] = 0ull;
            }
            picks++;
            __syncwarp();
        }
        if (tid == 0) {
            s_picks = picks;
            int k = picks, a = 0;
            while (k < TK) {
                bool used = false;
                for (int t = 0; t < picks; t++) if (s_win[t] == a) { used = true; break; }
                if (!used) { s_win[k] = a; s_val[k] = 0.f; k++; }
                a++;
            }
        }
        __syncwarp();

        if (tid < TK) {
            int   idx = s_win[tid];
            float val = s_val[tid];
            bool claim;
            float4 p;
            if (tid < s_picks) {
                claim = true;                    // m>0 implies in-box
                p = pd_bbox[b*NA + idx];
            } else {
                float2 ap = anc[idx];            // filler: in-box test required
                float dmin = fminf(fminf(ap.x - g.x, ap.y - g.y),
                                   fminf(g.z - ap.x, g.w - ap.y));
                claim = dmin > EPSF;
                if (claim) p = pd_bbox[b*NA + idx];
            }
            if (claim) {
                float parea = (p.z - p.x)*(p.w - p.y + EPSF);
                float iou = iou_f(g, garea, p, parea);
                int pp = b*NA + idx;
                atomicAdd(&g_count[pp], 1);
                int cp = atomicAdd(&g_claim_cnt, 1);
                if (cp < MAXCLAIM) g_claim[cp] = pp;
                // benign race: multi anchors fully rewritten in k_finalize
                g_cand_n[pp]     = n;
                g_cand_align[pp] = val;
                g_cand_ovl[pp]   = iou;
            }
        }
    }
}

// ---------------------------------------------------------------------------
// 3) finalize: resolve multi anchors (idempotent duplicates) + pos maxima
// ---------------------------------------------------------------------------
__global__ void k_finalize(const float* __restrict__ pd_scores,
                           const float4* __restrict__ pd_bbox,
                           const int* __restrict__ gt_labels,
                           const float4* __restrict__ gt_bbox) {
    int gid = blockIdx.x*256 + threadIdx.x;
    int mc = min(g_claim_cnt, MAXCLAIM);
    if (gid >= mc) return;
    int p = g_claim[gid];
    int b = p / NA, a = p % NA;
    int cn; float al, ov;
    if (g_count[p] > 1) {
        float4 pb = pd_bbox[p];
        float parea = (pb.z - pb.x)*(pb.w - pb.y + EPSF);
        float bv = -1.f; int bn = 0;
        for (int n = 0; n < NG; n++) {
            float4 gg = gt_bbox[b*NG + n];
            float ga = (gg.z - gg.x)*(gg.w - gg.y + EPSF);
            float v = iou_f(gg, ga, pb, parea);
            if (v > bv) { bv = v; bn = n; }
        }
        float sc = pd_scores[(b*NA + a)*NC + gt_labels[b*NG + bn]];
        float o2 = bv*bv;
        cn = bn; ov = bv; al = sc * o2*o2*o2;
        g_cand_n[p]     = cn;
        g_cand_ovl[p]   = ov;
        g_cand_align[p] = al;
    } else {
        cn = g_cand_n[p];
        al = g_cand_align[p];
        ov = g_cand_ovl[p];
    }
    atomicMax(&g_pos_align[b*NG + cn], __float_as_uint(al));
    atomicMax(&g_pos_ovl[b*NG + cn],   __float_as_uint(ov));
}

// ---------------------------------------------------------------------------
// 4) small outputs with per-block smem tables: no per-thread gathers, just
//    2 coalesced loads + smem lookups + coalesced stores + sparse scatter.
// ---------------------------------------------------------------------------
__global__ void k_small(const int* __restrict__ gt_labels,
                        const float4* __restrict__ gt_bbox,
                        float* __restrict__ out) {
    __shared__ int    s_lab[2*NG];
    __shared__ float4 s_box[2*NG];
    __shared__ float  s_pa[2*NG];
    __shared__ float  s_po[2*NG];

    int base = blockIdx.x * 256;
    int t = threadIdx.x;
    int b0 = base / NA;
    int bend = min(base + 255, BS*NA - 1) / NA;
    int nb = bend - b0 + 1;                        // 1 or 2 batches per block

    for (int i = t; i < nb*NG; i += 256) {
        int bb = b0 + i / NG;
        int n  = i % NG;
        s_lab[i] = gt_labels[bb*NG + n];
        s_box[i] = gt_bbox[bb*NG + n];
        s_pa[i]  = __uint_as_float(g_pos_align[bb*NG + n]);
        s_po[i]  = __uint_as_float(g_pos_ovl[bb*NG + n]);
    }
    __syncthreads();

    int gid = base + t;
    if (gid >= BS*NA) return;
    int boff = (gid / NA - b0) * NG;

    int cn = g_cand_n[gid];
    bool fg = cn >= 0;
    int tgt = fg ? cn : 0;
    int lab = s_lab[boff + tgt];

    out[OFF_LAB + gid] = (float)lab;
    ((float4*)(out + OFF_BOX))[gid] = s_box[boff + tgt];
    out[OFF_FG  + gid] = fg ? 1.f : 0.f;
    out[OFF_TGT + gid] = (float)tgt;
    if (fg) {
        float norm = g_cand_align[gid] * s_po[boff + cn] / (s_pa[boff + cn] + EPSF);
        out[OFF_SCR + gid*NC + lab] = norm;
    }
}

// ---------------------------------------------------------------------------
extern "C" void kernel_launch(void* const* d_in, const int* in_sizes, int n_in,
                              void* d_out, int out_size) {
    const float*  pd_scores = (const float*)d_in[0];
    const float4* pd_bbox   = (const float4*)d_in[1];
    const float2* anc       = (const float2*)d_in[2];
    const int*    gt_labels = (const int*)d_in[3];
    const float4* gt_bbox   = (const float4*)d_in[4];
    const float*  mask_gt   = (const float*)d_in[5];
    float* out = (float*)d_out;
    (void)in_sizes; (void)n_in; (void)out_size;

    k_prep<<<1 + ZS_BLK + ZSC_BLK, 1024>>>(anc, out);
    k_assign<<<BS*NG, 256>>>(pd_scores, pd_bbox, anc, mask_gt, gt_labels, gt_bbox);
    k_finalize<<<(MAXCLAIM + 255)/256, 256>>>(pd_scores, pd_bbox, gt_labels, gt_bbox);
    k_small<<<(BS*NA + 255)/256, 256>>>(gt_labels, gt_bbox, out);
}